// round 1
// baseline (speedup 1.0000x reference)
#include <cuda_runtime.h>
#include <math.h>

// Problem constants
#define BB   32      // batch
#define LL   1024    // seq len
#define CH   34      // raw channels
#define DD   256     // d_model
#define EE   8       // experts
#define PP   4       // patches actually needed (flat[:, :1024] slice)
#define PLEN 16      // patch length
#define PRED 96
#define RR   128     // BB*PP row-patches

// Scratch (device globals; no allocation allowed)
__device__ float g_xp[RR * DD];          // 128 KB
__device__ float g_gates[RR * EE];
__device__ float g_bias[RR * DD];        // gate-weighted expert bias
__device__ float g_part[EE * RR * DD];   // 1 MB, per-expert gated partials
__device__ float g_mean[BB];
__device__ float g_stdev[BB];

// ---------------------------------------------------------------------------
// Kernel 1: per-batch stats, patch projection, router softmax, gated bias.
// grid = 32 (one per batch b), block = 256
// ---------------------------------------------------------------------------
__global__ void k1_prep(const float* __restrict__ x,
                        const float* __restrict__ W_proj,
                        const float* __restrict__ b_proj,
                        const float* __restrict__ W_router,
                        const float* __restrict__ b_router,
                        const float* __restrict__ b_experts) {
    int b   = blockIdx.x;
    int tid = threadIdx.x;

    __shared__ float red[256];
    __shared__ float sh_xc[64];
    __shared__ float sh_xp[PP * DD];
    __shared__ float sh_rr[32][9];     // router partial sums (padded)
    __shared__ float sh_logit[32];
    __shared__ float sh_g[PP * EE];

    // Row = x[b, :, 2]  (only channel 2 feeds the output)
    const float* xb = x + (size_t)b * LL * CH + 2;
    float v[4];
#pragma unroll
    for (int i = 0; i < 4; i++) v[i] = xb[(size_t)(tid + 256 * i) * CH];

    // mean
    red[tid] = v[0] + v[1] + v[2] + v[3];
    __syncthreads();
    for (int off = 128; off > 0; off >>= 1) {
        if (tid < off) red[tid] += red[tid + off];
        __syncthreads();
    }
    float mean = red[0] * (1.0f / 1024.0f);
    __syncthreads();

    // variance of centered values
    float sq = 0.f;
#pragma unroll
    for (int i = 0; i < 4; i++) { float dv = v[i] - mean; sq += dv * dv; }
    red[tid] = sq;
    __syncthreads();
    for (int off = 128; off > 0; off >>= 1) {
        if (tid < off) red[tid] += red[tid + off];
        __syncthreads();
    }
    float var   = red[0] * (1.0f / 1024.0f);
    float stdev = sqrtf(var + 1e-5f);
    float rstd  = 1.0f / stdev;
    __syncthreads();

    // normalized first 64 samples (patches 0..3); thread tid<64 holds v[0]=x[l=tid]
    if (tid < 64) sh_xc[tid] = (v[0] - mean) * rstd;
    if (tid == 0) { g_mean[b] = mean; g_stdev[b] = stdev; }
    __syncthreads();

    // xp[p][dd] = b_proj[dd] + sum_k W_proj[dd][k] * xc[p*16+k]
    {
        int dd = tid;
        const float4* wrow = (const float4*)(W_proj + dd * 16);
        float4 w0 = wrow[0], w1 = wrow[1], w2 = wrow[2], w3 = wrow[3];
        float bp = b_proj[dd];
#pragma unroll
        for (int p = 0; p < PP; p++) {
            const float* xc = sh_xc + p * 16;
            float acc = bp;
            acc += w0.x * xc[0]  + w0.y * xc[1]  + w0.z * xc[2]  + w0.w * xc[3];
            acc += w1.x * xc[4]  + w1.y * xc[5]  + w1.z * xc[6]  + w1.w * xc[7];
            acc += w2.x * xc[8]  + w2.y * xc[9]  + w2.z * xc[10] + w2.w * xc[11];
            acc += w3.x * xc[12] + w3.y * xc[13] + w3.z * xc[14] + w3.w * xc[15];
            sh_xp[p * DD + dd] = acc;
            g_xp[(size_t)(b * PP + p) * DD + dd] = acc;
        }
    }
    __syncthreads();

    // router logits: 32 (p,e) pairs, 8 threads each over d-slices of 32
    {
        int pe = tid >> 3, sl = tid & 7;
        int p = pe >> 3, e = pe & 7;
        const float* wr = W_router + e * DD + sl * 32;
        const float* xp = sh_xp + p * DD + sl * 32;
        float acc = 0.f;
#pragma unroll
        for (int k = 0; k < 32; k += 4) {
            float4 w = *(const float4*)(wr + k);
            acc += w.x * xp[k] + w.y * xp[k + 1] + w.z * xp[k + 2] + w.w * xp[k + 3];
        }
        sh_rr[pe][sl] = acc;
    }
    __syncthreads();
    if (tid < 32) {
        float acc = b_router[tid & 7];
#pragma unroll
        for (int s = 0; s < 8; s++) acc += sh_rr[tid][s];
        sh_logit[tid] = acc;
    }
    __syncthreads();
    if (tid < PP) {
        int p = tid;
        float m = -1e30f;
#pragma unroll
        for (int e = 0; e < EE; e++) m = fmaxf(m, sh_logit[p * 8 + e]);
        float ex[EE], sum = 0.f;
#pragma unroll
        for (int e = 0; e < EE; e++) { ex[e] = expf(sh_logit[p * 8 + e] - m); sum += ex[e]; }
        float inv = 1.0f / sum;
#pragma unroll
        for (int e = 0; e < EE; e++) {
            float g = ex[e] * inv;
            sh_g[p * EE + e] = g;
            g_gates[(b * PP + p) * EE + e] = g;
        }
    }
    __syncthreads();

    // gate-weighted expert bias: g_bias[r][h] = sum_e g[p][e]*b_experts[e][h]
    {
        int h = tid;
        float be[EE];
#pragma unroll
        for (int e = 0; e < EE; e++) be[e] = b_experts[e * DD + h];
#pragma unroll
        for (int p = 0; p < PP; p++) {
            float acc = 0.f;
#pragma unroll
            for (int e = 0; e < EE; e++) acc += sh_g[p * EE + e] * be[e];
            g_bias[(size_t)(b * PP + p) * DD + h] = acc;
        }
    }
}

// ---------------------------------------------------------------------------
// Kernel 2: gated expert GEMM partials.
// part[e][r][h] = gates[r][e] * sum_d xp[r][d] * W_experts[e][h][d]
// grid = (8 experts, 4 h-tiles of 64, 4 r-tiles of 32), block = 256
// Shared-tiled NT GEMM, thread tile 2 rows x 4 cols, k staged in 64-chunks.
// ---------------------------------------------------------------------------
#define K2_STRIDE 68   // 272B row stride: 16B aligned, spreads banks

__global__ void k2_experts(const float* __restrict__ W_experts) {
    int e  = blockIdx.x;
    int hb = blockIdx.y;           // h0 = hb*64
    int rb = blockIdx.z;           // r0 = rb*32
    int tid = threadIdx.x;

    __shared__ float As[32 * K2_STRIDE];
    __shared__ float Ws[64 * K2_STRIDE];

    int tr = tid >> 4;             // 0..15 -> rows tr*2, tr*2+1
    int th = tid & 15;             // 0..15 -> cols th, th+16, th+32, th+48

    float acc[2][4] = {{0.f, 0.f, 0.f, 0.f}, {0.f, 0.f, 0.f, 0.f}};

    const float* Wb = W_experts + ((size_t)e * DD + hb * 64) * DD;
    const float* Ab = g_xp + (size_t)(rb * 32) * DD;

    for (int k0 = 0; k0 < DD; k0 += 64) {
        __syncthreads();
        // stage A: 32x64 floats
#pragma unroll
        for (int i = 0; i < 2; i++) {
            int q = tid + 256 * i;
            int row = q >> 4, c4 = q & 15;
            float4 av = *(const float4*)(Ab + row * DD + k0 + c4 * 4);
            *(float4*)(As + row * K2_STRIDE + c4 * 4) = av;
        }
        // stage W: 64x64 floats
#pragma unroll
        for (int i = 0; i < 4; i++) {
            int q = tid + 256 * i;
            int row = q >> 4, c4 = q & 15;
            float4 wv = *(const float4*)(Wb + row * DD + k0 + c4 * 4);
            *(float4*)(Ws + row * K2_STRIDE + c4 * 4) = wv;
        }
        __syncthreads();

#pragma unroll
        for (int kk = 0; kk < 64; kk += 4) {
            float4 a0 = *(const float4*)(As + (tr * 2)     * K2_STRIDE + kk);
            float4 a1 = *(const float4*)(As + (tr * 2 + 1) * K2_STRIDE + kk);
#pragma unroll
            for (int j = 0; j < 4; j++) {
                float4 w = *(const float4*)(Ws + (th + 16 * j) * K2_STRIDE + kk);
                acc[0][j] += a0.x * w.x + a0.y * w.y + a0.z * w.z + a0.w * w.w;
                acc[1][j] += a1.x * w.x + a1.y * w.y + a1.z * w.z + a1.w * w.w;
            }
        }
    }

#pragma unroll
    for (int i = 0; i < 2; i++) {
        int r = rb * 32 + tr * 2 + i;
        float ge = g_gates[r * EE + e];
#pragma unroll
        for (int j = 0; j < 4; j++) {
            int h = hb * 64 + th + 16 * j;
            g_part[((size_t)e * RR + r) * DD + h] = ge * acc[i][j];
        }
    }
}

// ---------------------------------------------------------------------------
// Kernel 3: reduce experts, re-scale (stdev/mean), fused head GEMV.
// out[b][j] = b_head[j] + sum_l W_head[j][l] * (comb[b][l]*stdev_b + mean_b)
// grid = 32 (batch), block = 128
// ---------------------------------------------------------------------------
__global__ void k3_head(const float* __restrict__ W_head,
                        const float* __restrict__ b_head,
                        float* __restrict__ out) {
    int b   = blockIdx.x;
    int tid = threadIdx.x;
    __shared__ float sf[LL];

    float mean  = g_mean[b];
    float stdev = g_stdev[b];

#pragma unroll
    for (int i = 0; i < 8; i++) {
        int l = tid + 128 * i;
        int p = l >> 8, h = l & 255;
        int r = b * PP + p;
        float v = g_bias[(size_t)r * DD + h];
#pragma unroll
        for (int e = 0; e < EE; e++) v += g_part[((size_t)e * RR + r) * DD + h];
        sf[l] = v * stdev + mean;
    }
    __syncthreads();

    if (tid < PRED) {
        const float* wr = W_head + (size_t)tid * LL;
        float a0 = 0.f, a1 = 0.f, a2 = 0.f, a3 = 0.f;
#pragma unroll 8
        for (int l = 0; l < LL; l += 4) {
            float4 w = *(const float4*)(wr + l);
            a0 += w.x * sf[l];
            a1 += w.y * sf[l + 1];
            a2 += w.z * sf[l + 2];
            a3 += w.w * sf[l + 3];
        }
        out[b * PRED + tid] = (a0 + a1) + (a2 + a3) + b_head[tid];
    }
}

// ---------------------------------------------------------------------------
extern "C" void kernel_launch(void* const* d_in, const int* in_sizes, int n_in,
                              void* d_out, int out_size) {
    const float* x         = (const float*)d_in[0];
    // d_in[1..3] = x_mark_enc, x_dec, x_mark_dec (unused by the model)
    const float* W_proj    = (const float*)d_in[4];
    const float* b_proj    = (const float*)d_in[5];
    const float* W_router  = (const float*)d_in[6];
    const float* b_router  = (const float*)d_in[7];
    const float* W_experts = (const float*)d_in[8];
    const float* b_experts = (const float*)d_in[9];
    const float* W_head    = (const float*)d_in[10];
    const float* b_head    = (const float*)d_in[11];
    float* out = (float*)d_out;

    k1_prep<<<BB, 256>>>(x, W_proj, b_proj, W_router, b_router, b_experts);
    dim3 g2(EE, 4, 4);
    k2_experts<<<g2, 256>>>(W_experts);
    k3_head<<<BB, 128>>>(W_head, b_head, out);
}

// round 2
// speedup vs baseline: 1.1252x; 1.1252x over previous
#include <cuda_runtime.h>
#include <math.h>
#include <stdint.h>

#define BB   32
#define LL   1024
#define CH   34
#define DD   256
#define EE   8
#define PP   4
#define PRED 96
#define RR   128
#define NBLK 128
#define NTHR 256

// dynamic smem layout (floats)
#define WS_STRIDE 260
#define AS_STRIDE 260
#define WS_FLOATS (64 * WS_STRIDE)            // 16640
#define AS_FLOATS (32 * AS_STRIDE)            // 8320
#define SMEM_FLOATS (WS_FLOATS + AS_FLOATS)   // 24960
#define SMEM_BYTES (SMEM_FLOATS * 4)          // 99840

// global scratch (no allocations allowed)
__device__ float g_xp[RR * DD];
__device__ float g_gates[RR * EE];
__device__ float g_bias[RR * DD];
__device__ float g_part[EE * RR * DD];
__device__ float g_mean[BB];
__device__ float g_std[BB];
__device__ float g_s1[NBLK];
__device__ float g_s2[NBLK];
__device__ unsigned g_barcnt[4];
__device__ float g_dummy[4];

__device__ __forceinline__ void cp16(void* dst_smem, const void* src_gmem) {
    uint32_t d = (uint32_t)__cvta_generic_to_shared(dst_smem);
    asm volatile("cp.async.cg.shared.global [%0], [%1], 16;" :: "r"(d), "l"(src_gmem));
}

// Sense-free monotonic grid barrier: each launch adds exactly 128 per slot,
// so the counter is always a multiple of 128 at launch start (graph-replay safe).
__device__ __forceinline__ void grid_barrier(int k) {
    __syncthreads();
    if (threadIdx.x == 0) {
        __threadfence();
        unsigned old = atomicAdd(&g_barcnt[k], 1u);
        unsigned target = (old & ~127u) + 128u;
        while (*((volatile unsigned*)&g_barcnt[k]) < target) {
            __nanosleep(128);
        }
        __threadfence();
    }
    __syncthreads();
}

__global__ void __launch_bounds__(NTHR, 1)
fused_kernel(const float* __restrict__ x,
             const float* __restrict__ W_proj,
             const float* __restrict__ b_proj,
             const float* __restrict__ W_router,
             const float* __restrict__ b_router,
             const float* __restrict__ W_experts,
             const float* __restrict__ b_experts,
             const float* __restrict__ W_head,
             const float* __restrict__ b_head,
             float* __restrict__ out) {
    extern __shared__ float sm[];
    float* Ws = sm;                    // 64 x 260
    float* As = sm + WS_FLOATS;        // 32 x 260, reused as scratch + sf
    float* scratch = As;

    const int bid = blockIdx.x;
    const int tid = threadIdx.x;

    // k2 tile coordinates (used at start for W staging, and in phase B)
    const int e2  = bid >> 4;
    const int hb2 = (bid >> 2) & 3;
    const int rb2 = bid & 3;

    // ---- issue W_experts tile staging immediately (overlaps all of phase A)
    {
        const float* Wb = W_experts + ((size_t)e2 * DD + hb2 * 64) * DD;
#pragma unroll
        for (int i = 0; i < 16; i++) {
            int q = tid + NTHR * i;
            int row = q >> 6, c4 = q & 63;
            cp16(Ws + row * WS_STRIDE + c4 * 4, Wb + row * DD + c4 * 4);
        }
        asm volatile("cp.async.commit_group;");
    }

    // ================= Phase A1: stats partials + L2 prefetch =================
    {
        int b = bid >> 2, q = bid & 3;
        float v = __ldg(x + ((size_t)(b * LL + q * 256 + tid)) * CH + 2);
        float s1 = v, s2 = v * v;

        // L2 prefetch by otherwise-idle-capacity blocks (overlaps gather latency)
        float pf = 0.f;
        if (bid == 32) {
            for (int i = tid; i < DD * 16; i += NTHR) pf += __ldg(W_proj + i);
            for (int i = tid; i < EE * DD; i += NTHR)
                pf += __ldg(W_router + i) + __ldg(b_experts + i);
            if (tid < DD)   pf += __ldg(b_proj + tid);
            if (tid < PRED) pf += __ldg(b_head + tid);
            if (tid < EE)   pf += __ldg(b_router + tid);
        }
        if (bid >= 64) {
            const float* wh = W_head + (size_t)(bid - 64) * 1536;
#pragma unroll
            for (int i = 0; i < 6; i++) pf += __ldg(wh + tid + 256 * i);
        }
        if (pf == 1.2345e-30f) g_dummy[0] = pf;   // keep prefetch loads alive

#pragma unroll
        for (int off = 16; off > 0; off >>= 1) {
            s1 += __shfl_xor_sync(0xffffffffu, s1, off);
            s2 += __shfl_xor_sync(0xffffffffu, s2, off);
        }
        __shared__ float r1[8], r2[8];
        if ((tid & 31) == 0) { r1[tid >> 5] = s1; r2[tid >> 5] = s2; }
        __syncthreads();
        if (tid == 0) {
            float a = 0.f, c = 0.f;
#pragma unroll
            for (int w = 0; w < 8; w++) { a += r1[w]; c += r2[w]; }
            g_s1[bid] = a;
            g_s2[bid] = c;
        }
    }
    grid_barrier(0);

    // ================= Phase A2: norm, xp, router, gated bias (blocks 0..31) ==
    if (bid < BB) {
        const int b = bid;
        float s1 = g_s1[b * 4 + 0] + g_s1[b * 4 + 1] + g_s1[b * 4 + 2] + g_s1[b * 4 + 3];
        float s2 = g_s2[b * 4 + 0] + g_s2[b * 4 + 1] + g_s2[b * 4 + 2] + g_s2[b * 4 + 3];
        float mean = s1 * (1.0f / 1024.0f);
        float var  = s2 * (1.0f / 1024.0f) - mean * mean;
        float stdev = sqrtf(var + 1e-5f);
        float rstd  = 1.0f / stdev;
        if (tid == 0) { g_mean[b] = mean; g_std[b] = stdev; }

        float* sxc  = scratch;          // 64
        float* sxp  = scratch + 64;     // 1024
        float* srr  = scratch + 1088;   // 32*9 = 288
        float* slog = scratch + 1376;   // 32
        float* sg   = scratch + 1408;   // 32

        if (tid < 64)
            sxc[tid] = (__ldg(x + ((size_t)(b * LL + tid)) * CH + 2) - mean) * rstd;
        __syncthreads();

        // xp[p][dd]
        {
            int dd = tid;
            const float4* wrow = (const float4*)(W_proj + dd * 16);
            float4 w0 = wrow[0], w1 = wrow[1], w2 = wrow[2], w3 = wrow[3];
            float bp = __ldg(b_proj + dd);
#pragma unroll
            for (int p = 0; p < PP; p++) {
                const float* xc = sxc + p * 16;
                float acc = bp;
                acc += w0.x * xc[0]  + w0.y * xc[1]  + w0.z * xc[2]  + w0.w * xc[3];
                acc += w1.x * xc[4]  + w1.y * xc[5]  + w1.z * xc[6]  + w1.w * xc[7];
                acc += w2.x * xc[8]  + w2.y * xc[9]  + w2.z * xc[10] + w2.w * xc[11];
                acc += w3.x * xc[12] + w3.y * xc[13] + w3.z * xc[14] + w3.w * xc[15];
                sxp[p * DD + dd] = acc;
                g_xp[(size_t)(b * PP + p) * DD + dd] = acc;
            }
        }
        __syncthreads();

        // router logits
        {
            int pe = tid >> 3, sl = tid & 7;
            int p = pe >> 3, e = pe & 7;
            const float* wr = W_router + e * DD + sl * 32;
            const float* xp = sxp + p * DD + sl * 32;
            float acc = 0.f;
#pragma unroll
            for (int k = 0; k < 32; k += 4) {
                float4 w = *(const float4*)(wr + k);
                acc += w.x * xp[k] + w.y * xp[k + 1] + w.z * xp[k + 2] + w.w * xp[k + 3];
            }
            srr[pe * 9 + sl] = acc;
        }
        __syncthreads();
        if (tid < 32) {
            float acc = __ldg(b_router + (tid & 7));
#pragma unroll
            for (int s = 0; s < 8; s++) acc += srr[tid * 9 + s];
            slog[tid] = acc;
        }
        __syncthreads();
        if (tid < PP) {
            int p = tid;
            float m = -1e30f;
#pragma unroll
            for (int e = 0; e < EE; e++) m = fmaxf(m, slog[p * 8 + e]);
            float ex[EE], sum = 0.f;
#pragma unroll
            for (int e = 0; e < EE; e++) { ex[e] = __expf(slog[p * 8 + e] - m); sum += ex[e]; }
            float inv = 1.0f / sum;
#pragma unroll
            for (int e = 0; e < EE; e++) {
                float g = ex[e] * inv;
                sg[p * EE + e] = g;
                g_gates[(b * PP + p) * EE + e] = g;
            }
        }
        __syncthreads();

        // gate-weighted expert bias
        {
            int h = tid;
            float be[EE];
#pragma unroll
            for (int e = 0; e < EE; e++) be[e] = __ldg(b_experts + e * DD + h);
#pragma unroll
            for (int p = 0; p < PP; p++) {
                float acc = 0.f;
#pragma unroll
                for (int e = 0; e < EE; e++) acc += sg[p * EE + e] * be[e];
                g_bias[(size_t)(b * PP + p) * DD + h] = acc;
            }
        }
    }
    grid_barrier(1);

    // ================= Phase B: gated expert GEMM partials =================
    {
        // stage A tile (32 rows x 256) from g_xp (L2-hot)
#pragma unroll
        for (int i = 0; i < 8; i++) {
            int q = tid + NTHR * i;
            int row = q >> 6, c4 = q & 63;
            float4 v = *(const float4*)(g_xp + (size_t)(rb2 * 32 + row) * DD + c4 * 4);
            *(float4*)(As + row * AS_STRIDE + c4 * 4) = v;
        }
        asm volatile("cp.async.wait_group 0;" ::: "memory");
        __syncthreads();

        int tr = tid >> 4;     // 0..15 -> rows tr*2, tr*2+1
        int th = tid & 15;     // cols th + 16j
        float acc[2][4] = {{0.f,0.f,0.f,0.f},{0.f,0.f,0.f,0.f}};

        const float* a0p = As + (tr * 2) * AS_STRIDE;
        const float* a1p = As + (tr * 2 + 1) * AS_STRIDE;
#pragma unroll 8
        for (int kk = 0; kk < DD; kk += 4) {
            float4 a0 = *(const float4*)(a0p + kk);
            float4 a1 = *(const float4*)(a1p + kk);
#pragma unroll
            for (int j = 0; j < 4; j++) {
                float4 w = *(const float4*)(Ws + (th + 16 * j) * WS_STRIDE + kk);
                acc[0][j] += a0.x * w.x + a0.y * w.y + a0.z * w.z + a0.w * w.w;
                acc[1][j] += a1.x * w.x + a1.y * w.y + a1.z * w.z + a1.w * w.w;
            }
        }

#pragma unroll
        for (int i = 0; i < 2; i++) {
            int r = rb2 * 32 + tr * 2 + i;
            float ge = g_gates[r * EE + e2];
#pragma unroll
            for (int j = 0; j < 4; j++) {
                int h = hb2 * 64 + th + 16 * j;
                g_part[((size_t)e2 * RR + r) * DD + h] = ge * acc[i][j];
            }
        }
    }
    grid_barrier(2);

    // ================= Phase C: expert reduce + rescale + head GEMV ==========
    {
        int b  = bid >> 2;
        int jt = bid & 3;
        float mean  = g_mean[b];
        float stdev = g_std[b];
        float* sf = scratch;   // 1024

#pragma unroll
        for (int i = 0; i < 4; i++) {
            int l = tid + NTHR * i;
            int p = l >> 8, h = l & 255;
            int r = b * PP + p;
            float v = g_bias[(size_t)r * DD + h];
#pragma unroll
            for (int e = 0; e < EE; e++) v += g_part[((size_t)e * RR + r) * DD + h];
            sf[l] = v * stdev + mean;
        }
        __syncthreads();

        if (tid < 192) {
            int g = tid >> 3, s = tid & 7;
            int j = jt * 24 + g;
            const float4* wr = (const float4*)(W_head + (size_t)j * LL + s * 128);
            const float4* sv = (const float4*)(sf + s * 128);
            float a = 0.f;
#pragma unroll 8
            for (int i = 0; i < 32; i++) {
                float4 w = wr[i], xv = sv[i];
                a += w.x * xv.x + w.y * xv.y + w.z * xv.z + w.w * xv.w;
            }
#pragma unroll
            for (int off = 4; off > 0; off >>= 1)
                a += __shfl_down_sync(0xffffffffu, a, off, 8);
            if (s == 0) out[b * PRED + j] = a + __ldg(b_head + j);
        }
    }
}

extern "C" void kernel_launch(void* const* d_in, const int* in_sizes, int n_in,
                              void* d_out, int out_size) {
    const float* x         = (const float*)d_in[0];
    const float* W_proj    = (const float*)d_in[4];
    const float* b_proj    = (const float*)d_in[5];
    const float* W_router  = (const float*)d_in[6];
    const float* b_router  = (const float*)d_in[7];
    const float* W_experts = (const float*)d_in[8];
    const float* b_experts = (const float*)d_in[9];
    const float* W_head    = (const float*)d_in[10];
    const float* b_head    = (const float*)d_in[11];
    float* out = (float*)d_out;

    cudaFuncSetAttribute(fused_kernel,
                         cudaFuncAttributeMaxDynamicSharedMemorySize, SMEM_BYTES);
    fused_kernel<<<NBLK, NTHR, SMEM_BYTES>>>(x, W_proj, b_proj, W_router, b_router,
                                             W_experts, b_experts, W_head, b_head, out);
}